// round 12
// baseline (speedup 1.0000x reference)
#include <cuda_runtime.h>
#include <cuda_bf16.h>
#include <math.h>
#include <stdint.h>

#define NB 1024   // n = H*W
#define DD 512    // d
#define BB 32     // batch

// ------------------------- device scratch (no allocs) -----------------------
// ONLY referenced from device code (host shadow symbols are poison under ATS).
__device__ __nv_bfloat16 g_XI_hi[(size_t)BB * NB * DD];  // [b][i][c]
__device__ __nv_bfloat16 g_XI_lo[(size_t)BB * NB * DD];
__device__ __nv_bfloat16 g_XC_hi[(size_t)BB * DD * NB];  // [b][c][i]
__device__ __nv_bfloat16 g_XC_lo[(size_t)BB * DD * NB];
__device__ float         g_S   [(size_t)BB * NB * NB];   // [b][i][j]
__device__ float         g_u[BB * NB];
__device__ float         g_v[BB * NB];

__device__ __forceinline__ uint32_t smem_u32(const void* p) {
    uint32_t a;
    asm("{ .reg .u64 t; cvta.to.shared.u64 t, %1; cvt.u32.u64 %0, t; }" : "=r"(a) : "l"(p));
    return a;
}

#define LDMATRIX_X4(r0, r1, r2, r3, addr) \
    asm volatile("ldmatrix.sync.aligned.m8n8.x4.shared.b16 {%0,%1,%2,%3}, [%4];" \
                 : "=r"(r0), "=r"(r1), "=r"(r2), "=r"(r3) : "r"(addr))

#define MMA_BF16(c, a, b) \
    asm volatile("mma.sync.aligned.m16n8k16.row.col.f32.bf16.bf16.f32 " \
                 "{%0,%1,%2,%3}, {%4,%5,%6,%7}, {%8,%9}, {%0,%1,%2,%3};" \
                 : "+f"((c)[0]), "+f"((c)[1]), "+f"((c)[2]), "+f"((c)[3]) \
                 : "r"((a)[0]), "r"((a)[1]), "r"((a)[2]), "r"((a)[3]), \
                   "r"((b)[0]), "r"((b)[1]))

#define CP_ASYNC16(sm, gp) \
    asm volatile("cp.async.cg.shared.global [%0], [%1], 16;" :: "r"(sm), "l"(gp))
#define CP_COMMIT() asm volatile("cp.async.commit_group;" ::: "memory")
#define CP_WAIT1()  asm volatile("cp.async.wait_group 1;" ::: "memory")
#define CP_WAIT0()  asm volatile("cp.async.wait_group 0;" ::: "memory")

// ---------------------------------------------------------------------------
// Kernel 1: pos-add + bf16 hi/lo split, stored in both layouts.
// ---------------------------------------------------------------------------
__global__ void split_kernel(const float* __restrict__ x,
                             const float* __restrict__ rowe,
                             const float* __restrict__ cole)
{
    const int b  = blockIdx.z;
    const int c0 = blockIdx.y * 32;
    const int i0 = blockIdx.x * 64;
    __shared__ __nv_bfloat16 shi[64][40];
    __shared__ __nv_bfloat16 slo[64][40];

    const int tid = threadIdx.x;
    const int tx = tid & 31;
    const int ty = tid >> 5;
    const size_t xbase = (size_t)b * DD * NB;

#pragma unroll
    for (int r = 0; r < 4; ++r) {
        int c = c0 + ty + r * 8;
        int i = i0 + tx * 2;
        float2 xv = *(const float2*)&x[xbase + (size_t)c * NB + i];
        int h0 = i >> 5, w0 = i & 31;
        int h1 = (i + 1) >> 5, w1 = (i + 1) & 31;
        float p0 = (c < 256) ? cole[w0 * 256 + c] : rowe[h0 * 256 + (c - 256)];
        float p1 = (c < 256) ? cole[w1 * 256 + c] : rowe[h1 * 256 + (c - 256)];
        float v0 = xv.x + p0, v1 = xv.y + p1;
        __nv_bfloat16 hb0 = __float2bfloat16(v0);
        __nv_bfloat16 lb0 = __float2bfloat16(v0 - __bfloat162float(hb0));
        __nv_bfloat16 hb1 = __float2bfloat16(v1);
        __nv_bfloat16 lb1 = __float2bfloat16(v1 - __bfloat162float(hb1));
        unsigned int hp = ((unsigned)__bfloat16_as_ushort(hb1) << 16) | __bfloat16_as_ushort(hb0);
        unsigned int lp = ((unsigned)__bfloat16_as_ushort(lb1) << 16) | __bfloat16_as_ushort(lb0);
        *(unsigned int*)&g_XC_hi[xbase + (size_t)c * NB + i] = hp;
        *(unsigned int*)&g_XC_lo[xbase + (size_t)c * NB + i] = lp;
        int cc = ty + r * 8;
        shi[tx * 2][cc] = hb0; shi[tx * 2 + 1][cc] = hb1;
        slo[tx * 2][cc] = lb0; slo[tx * 2 + 1][cc] = lb1;
    }
    __syncthreads();

    int ii = tid >> 2;
    int cs = (tid & 3) * 8;
    size_t obase = ((size_t)b * NB + i0 + ii) * DD + c0 + cs;
    uint4 ph, pl;
    unsigned short* hp = (unsigned short*)&ph;
    unsigned short* lp = (unsigned short*)&pl;
#pragma unroll
    for (int k = 0; k < 8; ++k) {
        hp[k] = __bfloat16_as_ushort(shi[ii][cs + k]);
        lp[k] = __bfloat16_as_ushort(slo[ii][cs + k]);
    }
    *(uint4*)&g_XI_hi[obase] = ph;
    *(uint4*)&g_XI_lo[obase] = pl;
}

// ---------------------------------------------------------------------------
// GEMM1: S = XI XI^T / sqrt(d). Symmetric: 36 upper-tri block pairs, mirror
// write via smem transpose. cp.async double-buffered, bf16x3 mma.sync.
// Diagonal blocks (bi==bj) reuse the A smem for B (skip half the staging).
// ---------------------------------------------------------------------------
__global__ __launch_bounds__(256, 2)
void s_gemm_kernel()
{
    extern __shared__ char dyn[];
    const uint32_t sbase = smem_u32(dyn);
    const int tid  = threadIdx.x;
    const int wid  = tid >> 5;
    const int lane = tid & 31;
    const int wm   = wid >> 1;
    const int wn   = wid & 1;
    const int b = blockIdx.y;

    int t = blockIdx.x, bi = 0;
    while (t >= 8 - bi) { t -= 8 - bi; ++bi; }
    const int bj = bi + t;
    const int m0 = bi * 128, n0 = bj * 128;
    const bool diag = (bi == bj);

    const __nv_bfloat16* Ah = g_XI_hi + (size_t)b * NB * DD + (size_t)m0 * DD;
    const __nv_bfloat16* Al = g_XI_lo + (size_t)b * NB * DD + (size_t)m0 * DD;
    const __nv_bfloat16* Bh = g_XI_hi + (size_t)b * NB * DD + (size_t)n0 * DD;
    const __nv_bfloat16* Bl = g_XI_lo + (size_t)b * NB * DD + (size_t)n0 * DD;

    float acc[2][8][4];
#pragma unroll
    for (int mt = 0; mt < 2; ++mt)
#pragma unroll
        for (int nt = 0; nt < 8; ++nt)
#pragma unroll
            for (int q = 0; q < 4; ++q) acc[mt][nt][q] = 0.f;

    const int narr = diag ? 2 : 4;
    auto stage = [&](int p, int kc) {
        const uint32_t sb = sbase + (uint32_t)p * 40960u;
        const __nv_bfloat16* srcs[4] = {Ah, Al, Bh, Bl};
        for (int a = 0; a < narr; ++a) {
            const __nv_bfloat16* g = srcs[a] + kc;
            const uint32_t ab = sb + (uint32_t)a * 10240u;
#pragma unroll
            for (int pass = 0; pass < 2; ++pass) {
                int q = pass * 256 + tid;
                int row = q >> 2, seg = q & 3;
                CP_ASYNC16(ab + (uint32_t)(row * 80 + seg * 16),
                           g + (size_t)row * DD + seg * 8);
            }
        }
        CP_COMMIT();
    };

    stage(0, 0);
    const int NCH = DD / 32;     // 16
    for (int kci = 0; kci < NCH; ++kci) {
        const int p = kci & 1;
        if (kci + 1 < NCH) stage(p ^ 1, (kci + 1) * 32);
        if (kci + 1 < NCH) { CP_WAIT1(); } else { CP_WAIT0(); }
        __syncthreads();

        const uint32_t sb = sbase + (uint32_t)p * 40960u;
        const uint32_t sa_h = sb, sa_l = sb + 10240u;
        const uint32_t sb_h = diag ? sa_h : sb + 20480u;
        const uint32_t sb_l = diag ? sa_l : sb + 30720u;
#pragma unroll
        for (int ks = 0; ks < 2; ++ks) {
            const int k0 = ks * 16;
            uint32_t fAh[2][4], fAl[2][4];
#pragma unroll
            for (int mt = 0; mt < 2; ++mt) {
                int row = wm * 32 + mt * 16 + (lane & 15);
                uint32_t off = (uint32_t)(row * 40 + k0 + (lane >> 4) * 8) * 2u;
                LDMATRIX_X4(fAh[mt][0], fAh[mt][1], fAh[mt][2], fAh[mt][3], sa_h + off);
                LDMATRIX_X4(fAl[mt][0], fAl[mt][1], fAl[mt][2], fAl[mt][3], sa_l + off);
            }
#pragma unroll
            for (int pp = 0; pp < 4; ++pp) {
                int nrow = wn * 64 + pp * 16 + (lane & 15);
                uint32_t off = (uint32_t)(nrow * 40 + k0 + (lane >> 4) * 8) * 2u;
                uint32_t h0, h1, h2, h3, l0, l1, l2, l3;
                LDMATRIX_X4(h0, h1, h2, h3, sb_h + off);
                LDMATRIX_X4(l0, l1, l2, l3, sb_l + off);
                uint32_t bh0[2] = {h0, h2}, bh1[2] = {h1, h3};
                uint32_t bl0[2] = {l0, l2}, bl1[2] = {l1, l3};
#pragma unroll
                for (int mt = 0; mt < 2; ++mt) {
                    MMA_BF16(acc[mt][2 * pp],     fAh[mt], bh0);
                    MMA_BF16(acc[mt][2 * pp],     fAh[mt], bl0);
                    MMA_BF16(acc[mt][2 * pp],     fAl[mt], bh0);
                    MMA_BF16(acc[mt][2 * pp + 1], fAh[mt], bh1);
                    MMA_BF16(acc[mt][2 * pp + 1], fAh[mt], bl1);
                    MMA_BF16(acc[mt][2 * pp + 1], fAl[mt], bh1);
                }
            }
        }
        __syncthreads();
    }

    const float scale = 0.044194173824159216f; // 1/sqrt(512)
    float* Sb = g_S + (size_t)b * NB * NB;

#pragma unroll
    for (int mt = 0; mt < 2; ++mt) {
        int r0 = m0 + wm * 32 + mt * 16 + (lane >> 2);
#pragma unroll
        for (int nt = 0; nt < 8; ++nt) {
            int c = n0 + wn * 64 + nt * 8 + (lane & 3) * 2;
            float2 w0 = make_float2(acc[mt][nt][0] * scale, acc[mt][nt][1] * scale);
            float2 w1 = make_float2(acc[mt][nt][2] * scale, acc[mt][nt][3] * scale);
            *(float2*)&Sb[(size_t)r0 * NB + c]       = w0;
            *(float2*)&Sb[(size_t)(r0 + 8) * NB + c] = w1;
        }
    }

    if (!diag) {
        float* Tsm = (float*)dyn;
#pragma unroll
        for (int mt = 0; mt < 2; ++mt) {
            int lr = wm * 32 + mt * 16 + (lane >> 2);
#pragma unroll
            for (int nt = 0; nt < 8; ++nt) {
                int lc = wn * 64 + nt * 8 + (lane & 3) * 2;
                Tsm[lr * 129 + lc]           = acc[mt][nt][0] * scale;
                Tsm[lr * 129 + lc + 1]       = acc[mt][nt][1] * scale;
                Tsm[(lr + 8) * 129 + lc]     = acc[mt][nt][2] * scale;
                Tsm[(lr + 8) * 129 + lc + 1] = acc[mt][nt][3] * scale;
            }
        }
        __syncthreads();
        int jr = tid >> 1;
        int hh = (tid & 1) * 64;
        float* dst = &Sb[(size_t)(n0 + jr) * NB + m0 + hh];
#pragma unroll
        for (int k0 = 0; k0 < 64; k0 += 4) {
            float4 w;
            w.x = Tsm[(hh + k0 + 0) * 129 + jr];
            w.y = Tsm[(hh + k0 + 1) * 129 + jr];
            w.z = Tsm[(hh + k0 + 2) * 129 + jr];
            w.w = Tsm[(hh + k0 + 3) * 129 + jr];
            *(float4*)&dst[k0] = w;
        }
    }
}

// ---------------------------------------------------------------------------
// GEMM2 v2: out[b][c][i] = sum_j XC[c][j] * exp(S[i][j]+u[i]+v[j])
// 512 threads, CTA tile m=256 (c) x n=128 (i), BK=32, 1 CTA/SM.
// B tile (exp) double-buffered; transform for chunk k+1 overlaps MMA of k.
// dyn smem:
//   0      : A [2 stages][Ah(20480) Al(20480)]  = 81920
//   81920  : S [2 stages][128*144 f32]          = 36864
//   118784 : B [2 bufs][hi(10240) lo(10240)]    = 40960
//   total 159744
// ---------------------------------------------------------------------------
__global__ __launch_bounds__(512, 1)
void out_gemm_kernel(float* __restrict__ Dout)
{
    extern __shared__ char dyn[];
    const uint32_t sbase = smem_u32(dyn);
    const uint32_t sS0 = sbase + 81920u;
    const uint32_t sB0 = sbase + 118784u;

    const int tid  = threadIdx.x;
    const int wid  = tid >> 5;
    const int lane = tid & 31;
    const int wm   = wid >> 1;          // 0..7 (32 rows each)
    const int wn   = wid & 1;
    const int b  = blockIdx.z;
    const int n0 = blockIdx.x * 128;    // i block
    const int m0 = blockIdx.y * 256;    // c block

    const __nv_bfloat16* Ah = g_XC_hi + (size_t)b * DD * NB + (size_t)m0 * NB;
    const __nv_bfloat16* Al = g_XC_lo + (size_t)b * DD * NB + (size_t)m0 * NB;
    const float* Sb = g_S + (size_t)b * NB * NB + (size_t)n0 * NB;
    const float* vb = g_v + b * NB;
    const float  uu = g_u[b * NB + n0 + (tid >> 2)];   // for transform row

    float acc[2][8][4];
#pragma unroll
    for (int mt = 0; mt < 2; ++mt)
#pragma unroll
        for (int nt = 0; nt < 8; ++nt)
#pragma unroll
            for (int q = 0; q < 4; ++q) acc[mt][nt][q] = 0.f;

    auto stage = [&](int p, int kc) {
        // A hi/lo: 256 rows x 4 segs = 1024 per array -> 2 passes of 512
        const __nv_bfloat16* srcs[2] = {Ah, Al};
#pragma unroll
        for (int a = 0; a < 2; ++a) {
            const __nv_bfloat16* g = srcs[a] + kc;
            const uint32_t ab = sbase + (uint32_t)p * 40960u + (uint32_t)a * 20480u;
#pragma unroll
            for (int pass = 0; pass < 2; ++pass) {
                int q = pass * 512 + tid;
                int row = q >> 2, seg = q & 3;
                CP_ASYNC16(ab + (uint32_t)(row * 80 + seg * 16),
                           g + (size_t)row * NB + seg * 8);
            }
        }
        // S: 128 rows x 8 segs = 1024 -> 2 passes of 512
        const float* gs = Sb + kc;
        const uint32_t ss = sS0 + (uint32_t)p * 18432u;
#pragma unroll
        for (int pass = 0; pass < 2; ++pass) {
            int q = pass * 512 + tid;
            int row = q >> 3, seg = q & 7;
            CP_ASYNC16(ss + (uint32_t)(row * 144 + seg * 16),
                       gs + (size_t)row * NB + seg * 4);
        }
        CP_COMMIT();
    };

    // transform: B[q] = split(exp(S[sp] + u + v)); 8 values per thread
    auto transform = [&](int sp, int q, int kc) {
        const int row = tid >> 2, quarter = tid & 3;
        const uint32_t srow = sS0 + (uint32_t)sp * 18432u
                            + (uint32_t)(row * 144 + quarter * 32);
        float sv[8];
        asm volatile("ld.shared.v4.f32 {%0,%1,%2,%3}, [%4];"
                     : "=f"(sv[0]), "=f"(sv[1]), "=f"(sv[2]), "=f"(sv[3])
                     : "r"(srow));
        asm volatile("ld.shared.v4.f32 {%0,%1,%2,%3}, [%4];"
                     : "=f"(sv[4]), "=f"(sv[5]), "=f"(sv[6]), "=f"(sv[7])
                     : "r"(srow + 16u));
        const float* vp = vb + kc + quarter * 8;
        float4 v0 = *(const float4*)vp;
        float4 v1 = *(const float4*)(vp + 4);
        float vv[8] = {v0.x, v0.y, v0.z, v0.w, v1.x, v1.y, v1.z, v1.w};
        uint32_t hp[4], lp[4];
#pragma unroll
        for (int e = 0; e < 4; ++e) {
            float e0 = __expf(sv[2 * e]     + uu + vv[2 * e]);
            float e1 = __expf(sv[2 * e + 1] + uu + vv[2 * e + 1]);
            __nv_bfloat16 h0 = __float2bfloat16(e0);
            __nv_bfloat16 h1 = __float2bfloat16(e1);
            __nv_bfloat16 l0 = __float2bfloat16(e0 - __bfloat162float(h0));
            __nv_bfloat16 l1 = __float2bfloat16(e1 - __bfloat162float(h1));
            hp[e] = ((unsigned)__bfloat16_as_ushort(h1) << 16) | __bfloat16_as_ushort(h0);
            lp[e] = ((unsigned)__bfloat16_as_ushort(l1) << 16) | __bfloat16_as_ushort(l0);
        }
        const uint32_t bb = sB0 + (uint32_t)q * 20480u;
        const uint32_t bo = (uint32_t)(row * 80 + quarter * 16);
        asm volatile("st.shared.v4.b32 [%0], {%1,%2,%3,%4};"
                     :: "r"(bb + bo), "r"(hp[0]), "r"(hp[1]), "r"(hp[2]), "r"(hp[3]));
        asm volatile("st.shared.v4.b32 [%0], {%1,%2,%3,%4};"
                     :: "r"(bb + 10240u + bo), "r"(lp[0]), "r"(lp[1]), "r"(lp[2]), "r"(lp[3]));
    };

    // prologue: stage chunk 0, transform into B[0]
    stage(0, 0);
    CP_WAIT0();
    __syncthreads();
    transform(0, 0, 0);
    __syncthreads();

    const int NCH = NB / 32;    // 32
    for (int kci = 0; kci < NCH; ++kci) {
        const int p = kci & 1;
        if (kci + 1 < NCH) stage(p ^ 1, (kci + 1) * 32);

        // ---- MMAs on chunk kci: A[p], B[p] ----
        const uint32_t sa_h = sbase + (uint32_t)p * 40960u;
        const uint32_t sa_l = sa_h + 20480u;
        const uint32_t sb_h = sB0 + (uint32_t)p * 20480u;
        const uint32_t sb_l = sb_h + 10240u;
#pragma unroll
        for (int ks = 0; ks < 2; ++ks) {
            const int k0 = ks * 16;
            uint32_t fAh[2][4], fAl[2][4];
#pragma unroll
            for (int mt = 0; mt < 2; ++mt) {
                int row = wm * 32 + mt * 16 + (lane & 15);
                uint32_t off = (uint32_t)(row * 40 + k0 + (lane >> 4) * 8) * 2u;
                LDMATRIX_X4(fAh[mt][0], fAh[mt][1], fAh[mt][2], fAh[mt][3], sa_h + off);
                LDMATRIX_X4(fAl[mt][0], fAl[mt][1], fAl[mt][2], fAl[mt][3], sa_l + off);
            }
#pragma unroll
            for (int pp = 0; pp < 4; ++pp) {
                int nrow = wn * 64 + pp * 16 + (lane & 15);
                uint32_t off = (uint32_t)(nrow * 40 + k0 + (lane >> 4) * 8) * 2u;
                uint32_t h0, h1, h2, h3, l0, l1, l2, l3;
                LDMATRIX_X4(h0, h1, h2, h3, sb_h + off);
                LDMATRIX_X4(l0, l1, l2, l3, sb_l + off);
                uint32_t bh0[2] = {h0, h2}, bh1[2] = {h1, h3};
                uint32_t bl0[2] = {l0, l2}, bl1[2] = {l1, l3};
#pragma unroll
                for (int mt = 0; mt < 2; ++mt) {
                    MMA_BF16(acc[mt][2 * pp],     fAh[mt], bh0);
                    MMA_BF16(acc[mt][2 * pp],     fAh[mt], bl0);
                    MMA_BF16(acc[mt][2 * pp],     fAl[mt], bh0);
                    MMA_BF16(acc[mt][2 * pp + 1], fAh[mt], bh1);
                    MMA_BF16(acc[mt][2 * pp + 1], fAh[mt], bl1);
                    MMA_BF16(acc[mt][2 * pp + 1], fAl[mt], bh1);
                }
            }
        }

        if (kci + 1 < NCH) {
            CP_WAIT0();
            __syncthreads();                      // S[p^1] visible; MMAs done
            transform(p ^ 1, p ^ 1, (kci + 1) * 32);
            __syncthreads();                      // B[p^1] visible
        }
    }

    float* Db = Dout + (size_t)b * DD * NB;
#pragma unroll
    for (int mt = 0; mt < 2; ++mt) {
        int r0 = m0 + wm * 32 + mt * 16 + (lane >> 2);
#pragma unroll
        for (int nt = 0; nt < 8; ++nt) {
            int c = n0 + wn * 64 + nt * 8 + (lane & 3) * 2;
            float2 w0 = make_float2(acc[mt][nt][0], acc[mt][nt][1]);
            float2 w1 = make_float2(acc[mt][nt][2], acc[mt][nt][3]);
            *(float2*)&Db[(size_t)r0 * NB + c]       = w0;
            *(float2*)&Db[(size_t)(r0 + 8) * NB + c] = w1;
        }
    }
}

// ---------------------------------------------------------------------------
// u[b][i] = -log n - LSE_j S[b][i][:]   (warp per row)
// ---------------------------------------------------------------------------
__global__ void u_lse_kernel()
{
    const int gw   = blockIdx.x * 8 + (threadIdx.x >> 5);
    const int lane = threadIdx.x & 31;
    const float4* row = (const float4*)&g_S[(size_t)gw * NB];

    float4 V[8];
#pragma unroll
    for (int s = 0; s < 8; ++s) V[s] = row[lane + 32 * s];

    float m = -1e30f;
#pragma unroll
    for (int s = 0; s < 8; ++s)
        m = fmaxf(m, fmaxf(fmaxf(V[s].x, V[s].y), fmaxf(V[s].z, V[s].w)));
#pragma unroll
    for (int o = 16; o > 0; o >>= 1) m = fmaxf(m, __shfl_xor_sync(~0u, m, o));

    float sum = 0.f;
#pragma unroll
    for (int s = 0; s < 8; ++s)
        sum += __expf(V[s].x - m) + __expf(V[s].y - m) + __expf(V[s].z - m) + __expf(V[s].w - m);
#pragma unroll
    for (int o = 16; o > 0; o >>= 1) sum += __shfl_xor_sync(~0u, sum, o);

    if (lane == 0) g_u[gw] = -6.9314718055994531f - (m + logf(sum));
}

// ---------------------------------------------------------------------------
// v[b][j] = -log n - LSE_i (S[b][i][j] + u[b][i])  via symmetry (row j)
// ---------------------------------------------------------------------------
__global__ void v_lse_kernel()
{
    const int gw   = blockIdx.x * 8 + (threadIdx.x >> 5);
    const int lane = threadIdx.x & 31;
    const int b    = gw >> 10;
    const float4* row = (const float4*)&g_S[(size_t)gw * NB];
    const float4* urw = (const float4*)&g_u[b * NB];

    float4 V[8];
#pragma unroll
    for (int s = 0; s < 8; ++s) {
        float4 sv = row[lane + 32 * s];
        float4 uv = urw[lane + 32 * s];
        V[s].x = sv.x + uv.x; V[s].y = sv.y + uv.y;
        V[s].z = sv.z + uv.z; V[s].w = sv.w + uv.w;
    }
    float m = -1e30f;
#pragma unroll
    for (int s = 0; s < 8; ++s)
        m = fmaxf(m, fmaxf(fmaxf(V[s].x, V[s].y), fmaxf(V[s].z, V[s].w)));
#pragma unroll
    for (int o = 16; o > 0; o >>= 1) m = fmaxf(m, __shfl_xor_sync(~0u, m, o));

    float sum = 0.f;
#pragma unroll
    for (int s = 0; s < 8; ++s)
        sum += __expf(V[s].x - m) + __expf(V[s].y - m) + __expf(V[s].z - m) + __expf(V[s].w - m);
#pragma unroll
    for (int o = 16; o > 0; o >>= 1) sum += __shfl_xor_sync(~0u, sum, o);

    if (lane == 0) g_v[gw] = -6.9314718055994531f - (m + logf(sum));
}

// ---------------------------------------------------------------------------
extern "C" void kernel_launch(void* const* d_in, const int* in_sizes, int n_in,
                              void* d_out, int out_size)
{
    const float* x    = (const float*)d_in[0];
    const float* rowe = (const float*)d_in[1];
    const float* cole = (const float*)d_in[2];
    float* out = (float*)d_out;

    cudaFuncSetAttribute(s_gemm_kernel,   cudaFuncAttributeMaxDynamicSharedMemorySize, 81920);
    cudaFuncSetAttribute(out_gemm_kernel, cudaFuncAttributeMaxDynamicSharedMemorySize, 159744);

    // 1) pos add + bf16 split, both layouts
    split_kernel<<<dim3(NB / 64, DD / 32, BB), 256>>>(x, rowe, cole);

    // 2) S = XI XI^T / sqrt(d), symmetric (36 block pairs), pipelined
    s_gemm_kernel<<<dim3(36, BB), 256, 81920>>>();

    // 3) u = -log n - rowLSE(S)
    u_lse_kernel<<<BB * NB / 8, 256>>>();

    // 4) v = -log n - colLSE(S + u)  (symmetry)
    v_lse_kernel<<<BB * NB / 8, 256>>>();

    // 5) out = XC @ exp(S+u+v)^T, m=256 tiles, transform overlapped
    out_gemm_kernel<<<dim3(8, 2, BB), 512, 159744>>>(out);
}

// round 13
// speedup vs baseline: 1.1223x; 1.1223x over previous
#include <cuda_runtime.h>
#include <cuda_bf16.h>
#include <math.h>
#include <stdint.h>

#define NB 1024   // n = H*W
#define DD 512    // d
#define BB 32     // batch

// ------------------------- device scratch (no allocs) -----------------------
// ONLY referenced from device code (host shadow symbols are poison under ATS).
__device__ __nv_bfloat16 g_XI_hi[(size_t)BB * NB * DD];  // [b][i][c]
__device__ __nv_bfloat16 g_XI_lo[(size_t)BB * NB * DD];
__device__ __nv_bfloat16 g_XC_hi[(size_t)BB * DD * NB];  // [b][c][i]
__device__ __nv_bfloat16 g_XC_lo[(size_t)BB * DD * NB];
__device__ float         g_S   [(size_t)BB * NB * NB];   // [b][i][j]
__device__ float         g_u[BB * NB];
__device__ float         g_v[BB * NB];

__device__ __forceinline__ uint32_t smem_u32(const void* p) {
    uint32_t a;
    asm("{ .reg .u64 t; cvta.to.shared.u64 t, %1; cvt.u32.u64 %0, t; }" : "=r"(a) : "l"(p));
    return a;
}

#define LDMATRIX_X4(r0, r1, r2, r3, addr) \
    asm volatile("ldmatrix.sync.aligned.m8n8.x4.shared.b16 {%0,%1,%2,%3}, [%4];" \
                 : "=r"(r0), "=r"(r1), "=r"(r2), "=r"(r3) : "r"(addr))

#define MMA_BF16(c, a, b) \
    asm volatile("mma.sync.aligned.m16n8k16.row.col.f32.bf16.bf16.f32 " \
                 "{%0,%1,%2,%3}, {%4,%5,%6,%7}, {%8,%9}, {%0,%1,%2,%3};" \
                 : "+f"((c)[0]), "+f"((c)[1]), "+f"((c)[2]), "+f"((c)[3]) \
                 : "r"((a)[0]), "r"((a)[1]), "r"((a)[2]), "r"((a)[3]), \
                   "r"((b)[0]), "r"((b)[1]))

#define CP_ASYNC16(sm, gp) \
    asm volatile("cp.async.cg.shared.global [%0], [%1], 16;" :: "r"(sm), "l"(gp))
#define CP_COMMIT() asm volatile("cp.async.commit_group;" ::: "memory")
#define CP_WAIT1()  asm volatile("cp.async.wait_group 1;" ::: "memory")
#define CP_WAIT0()  asm volatile("cp.async.wait_group 0;" ::: "memory")

// ---------------------------------------------------------------------------
// Kernel 1: pos-add + bf16 hi/lo split, stored in both layouts.
// ---------------------------------------------------------------------------
__global__ void split_kernel(const float* __restrict__ x,
                             const float* __restrict__ rowe,
                             const float* __restrict__ cole)
{
    const int b  = blockIdx.z;
    const int c0 = blockIdx.y * 32;
    const int i0 = blockIdx.x * 64;
    __shared__ __nv_bfloat16 shi[64][40];
    __shared__ __nv_bfloat16 slo[64][40];

    const int tid = threadIdx.x;
    const int tx = tid & 31;
    const int ty = tid >> 5;
    const size_t xbase = (size_t)b * DD * NB;

#pragma unroll
    for (int r = 0; r < 4; ++r) {
        int c = c0 + ty + r * 8;
        int i = i0 + tx * 2;
        float2 xv = *(const float2*)&x[xbase + (size_t)c * NB + i];
        int h0 = i >> 5, w0 = i & 31;
        int h1 = (i + 1) >> 5, w1 = (i + 1) & 31;
        float p0 = (c < 256) ? cole[w0 * 256 + c] : rowe[h0 * 256 + (c - 256)];
        float p1 = (c < 256) ? cole[w1 * 256 + c] : rowe[h1 * 256 + (c - 256)];
        float v0 = xv.x + p0, v1 = xv.y + p1;
        __nv_bfloat16 hb0 = __float2bfloat16(v0);
        __nv_bfloat16 lb0 = __float2bfloat16(v0 - __bfloat162float(hb0));
        __nv_bfloat16 hb1 = __float2bfloat16(v1);
        __nv_bfloat16 lb1 = __float2bfloat16(v1 - __bfloat162float(hb1));
        unsigned int hp = ((unsigned)__bfloat16_as_ushort(hb1) << 16) | __bfloat16_as_ushort(hb0);
        unsigned int lp = ((unsigned)__bfloat16_as_ushort(lb1) << 16) | __bfloat16_as_ushort(lb0);
        *(unsigned int*)&g_XC_hi[xbase + (size_t)c * NB + i] = hp;
        *(unsigned int*)&g_XC_lo[xbase + (size_t)c * NB + i] = lp;
        int cc = ty + r * 8;
        shi[tx * 2][cc] = hb0; shi[tx * 2 + 1][cc] = hb1;
        slo[tx * 2][cc] = lb0; slo[tx * 2 + 1][cc] = lb1;
    }
    __syncthreads();

    int ii = tid >> 2;
    int cs = (tid & 3) * 8;
    size_t obase = ((size_t)b * NB + i0 + ii) * DD + c0 + cs;
    uint4 ph, pl;
    unsigned short* hp = (unsigned short*)&ph;
    unsigned short* lp = (unsigned short*)&pl;
#pragma unroll
    for (int k = 0; k < 8; ++k) {
        hp[k] = __bfloat16_as_ushort(shi[ii][cs + k]);
        lp[k] = __bfloat16_as_ushort(slo[ii][cs + k]);
    }
    *(uint4*)&g_XI_hi[obase] = ph;
    *(uint4*)&g_XI_lo[obase] = pl;
}

// ---------------------------------------------------------------------------
// GEMM1: S = XI XI^T / sqrt(d). Symmetric: 36 upper-tri block pairs, mirror
// write via smem transpose. cp.async double-buffered, bf16x3 mma.sync.
// Diagonal blocks reuse A smem for B (skip half the staging).
// ---------------------------------------------------------------------------
__global__ __launch_bounds__(256, 2)
void s_gemm_kernel()
{
    extern __shared__ char dyn[];
    const uint32_t sbase = smem_u32(dyn);
    const int tid  = threadIdx.x;
    const int wid  = tid >> 5;
    const int lane = tid & 31;
    const int wm   = wid >> 1;
    const int wn   = wid & 1;
    const int b = blockIdx.y;

    int t = blockIdx.x, bi = 0;
    while (t >= 8 - bi) { t -= 8 - bi; ++bi; }
    const int bj = bi + t;
    const int m0 = bi * 128, n0 = bj * 128;
    const bool diag = (bi == bj);

    const __nv_bfloat16* Ah = g_XI_hi + (size_t)b * NB * DD + (size_t)m0 * DD;
    const __nv_bfloat16* Al = g_XI_lo + (size_t)b * NB * DD + (size_t)m0 * DD;
    const __nv_bfloat16* Bh = g_XI_hi + (size_t)b * NB * DD + (size_t)n0 * DD;
    const __nv_bfloat16* Bl = g_XI_lo + (size_t)b * NB * DD + (size_t)n0 * DD;

    float acc[2][8][4];
#pragma unroll
    for (int mt = 0; mt < 2; ++mt)
#pragma unroll
        for (int nt = 0; nt < 8; ++nt)
#pragma unroll
            for (int q = 0; q < 4; ++q) acc[mt][nt][q] = 0.f;

    const int narr = diag ? 2 : 4;
    auto stage = [&](int p, int kc) {
        const uint32_t sb = sbase + (uint32_t)p * 40960u;
        const __nv_bfloat16* srcs[4] = {Ah, Al, Bh, Bl};
        for (int a = 0; a < narr; ++a) {
            const __nv_bfloat16* g = srcs[a] + kc;
            const uint32_t ab = sb + (uint32_t)a * 10240u;
#pragma unroll
            for (int pass = 0; pass < 2; ++pass) {
                int q = pass * 256 + tid;
                int row = q >> 2, seg = q & 3;
                CP_ASYNC16(ab + (uint32_t)(row * 80 + seg * 16),
                           g + (size_t)row * DD + seg * 8);
            }
        }
        CP_COMMIT();
    };

    stage(0, 0);
    const int NCH = DD / 32;     // 16
    for (int kci = 0; kci < NCH; ++kci) {
        const int p = kci & 1;
        if (kci + 1 < NCH) stage(p ^ 1, (kci + 1) * 32);
        if (kci + 1 < NCH) { CP_WAIT1(); } else { CP_WAIT0(); }
        __syncthreads();

        const uint32_t sb = sbase + (uint32_t)p * 40960u;
        const uint32_t sa_h = sb, sa_l = sb + 10240u;
        const uint32_t sb_h = diag ? sa_h : sb + 20480u;
        const uint32_t sb_l = diag ? sa_l : sb + 30720u;
#pragma unroll
        for (int ks = 0; ks < 2; ++ks) {
            const int k0 = ks * 16;
            uint32_t fAh[2][4], fAl[2][4];
#pragma unroll
            for (int mt = 0; mt < 2; ++mt) {
                int row = wm * 32 + mt * 16 + (lane & 15);
                uint32_t off = (uint32_t)(row * 40 + k0 + (lane >> 4) * 8) * 2u;
                LDMATRIX_X4(fAh[mt][0], fAh[mt][1], fAh[mt][2], fAh[mt][3], sa_h + off);
                LDMATRIX_X4(fAl[mt][0], fAl[mt][1], fAl[mt][2], fAl[mt][3], sa_l + off);
            }
#pragma unroll
            for (int pp = 0; pp < 4; ++pp) {
                int nrow = wn * 64 + pp * 16 + (lane & 15);
                uint32_t off = (uint32_t)(nrow * 40 + k0 + (lane >> 4) * 8) * 2u;
                uint32_t h0, h1, h2, h3, l0, l1, l2, l3;
                LDMATRIX_X4(h0, h1, h2, h3, sb_h + off);
                LDMATRIX_X4(l0, l1, l2, l3, sb_l + off);
                uint32_t bh0[2] = {h0, h2}, bh1[2] = {h1, h3};
                uint32_t bl0[2] = {l0, l2}, bl1[2] = {l1, l3};
#pragma unroll
                for (int mt = 0; mt < 2; ++mt) {
                    MMA_BF16(acc[mt][2 * pp],     fAh[mt], bh0);
                    MMA_BF16(acc[mt][2 * pp],     fAh[mt], bl0);
                    MMA_BF16(acc[mt][2 * pp],     fAl[mt], bh0);
                    MMA_BF16(acc[mt][2 * pp + 1], fAh[mt], bh1);
                    MMA_BF16(acc[mt][2 * pp + 1], fAh[mt], bl1);
                    MMA_BF16(acc[mt][2 * pp + 1], fAl[mt], bh1);
                }
            }
        }
        __syncthreads();
    }

    const float scale = 0.044194173824159216f; // 1/sqrt(512)
    float* Sb = g_S + (size_t)b * NB * NB;

#pragma unroll
    for (int mt = 0; mt < 2; ++mt) {
        int r0 = m0 + wm * 32 + mt * 16 + (lane >> 2);
#pragma unroll
        for (int nt = 0; nt < 8; ++nt) {
            int c = n0 + wn * 64 + nt * 8 + (lane & 3) * 2;
            float2 w0 = make_float2(acc[mt][nt][0] * scale, acc[mt][nt][1] * scale);
            float2 w1 = make_float2(acc[mt][nt][2] * scale, acc[mt][nt][3] * scale);
            *(float2*)&Sb[(size_t)r0 * NB + c]       = w0;
            *(float2*)&Sb[(size_t)(r0 + 8) * NB + c] = w1;
        }
    }

    if (!diag) {
        float* Tsm = (float*)dyn;
#pragma unroll
        for (int mt = 0; mt < 2; ++mt) {
            int lr = wm * 32 + mt * 16 + (lane >> 2);
#pragma unroll
            for (int nt = 0; nt < 8; ++nt) {
                int lc = wn * 64 + nt * 8 + (lane & 3) * 2;
                Tsm[lr * 129 + lc]           = acc[mt][nt][0] * scale;
                Tsm[lr * 129 + lc + 1]       = acc[mt][nt][1] * scale;
                Tsm[(lr + 8) * 129 + lc]     = acc[mt][nt][2] * scale;
                Tsm[(lr + 8) * 129 + lc + 1] = acc[mt][nt][3] * scale;
            }
        }
        __syncthreads();
        int jr = tid >> 1;
        int hh = (tid & 1) * 64;
        float* dst = &Sb[(size_t)(n0 + jr) * NB + m0 + hh];
#pragma unroll
        for (int k0 = 0; k0 < 64; k0 += 4) {
            float4 w;
            w.x = Tsm[(hh + k0 + 0) * 129 + jr];
            w.y = Tsm[(hh + k0 + 1) * 129 + jr];
            w.z = Tsm[(hh + k0 + 2) * 129 + jr];
            w.w = Tsm[(hh + k0 + 3) * 129 + jr];
            *(float4*)&dst[k0] = w;
        }
    }
}

// ---------------------------------------------------------------------------
// GEMM2 v3: out[b][c][i] = sum_j XC[c][j] * exp(S[i][j]+u[i]+v[j])
// 256 threads, tile m=128 x n=128, BK=32, 2 CTAs/SM.
// 3-stage cp.async pipeline; exp transform done IN PLACE in the S stage
// buffer (f32 -> packed bf16 hi/lo), XOR-swizzled 128B rows.
// Per stage: A(hi,lo) 20480 B + S/B 16384 B = 36864; x3 = 110592 B.
// Logical bf16 row layout after transform:
//   [hi k0..15 | lo k0..15 | hi k16..31 | lo k16..31]  (16B seg index 0..7)
// physical seg = logical seg ^ (row & 7).
// ---------------------------------------------------------------------------
__global__ __launch_bounds__(256, 2)
void out_gemm_kernel(float* __restrict__ Dout)
{
    extern __shared__ char dyn[];
    const uint32_t sbase = smem_u32(dyn);

    const int tid  = threadIdx.x;
    const int wid  = tid >> 5;
    const int lane = tid & 31;
    const int wm   = wid >> 1;
    const int wn   = wid & 1;
    const int b  = blockIdx.z;
    const int n0 = blockIdx.x * 128;   // i block
    const int m0 = blockIdx.y * 128;   // c block

    const __nv_bfloat16* Ah = g_XC_hi + (size_t)b * DD * NB + (size_t)m0 * NB;
    const __nv_bfloat16* Al = g_XC_lo + (size_t)b * DD * NB + (size_t)m0 * NB;
    const float* Sg = g_S + (size_t)b * NB * NB + (size_t)n0 * NB;
    const float* vb = g_v + b * NB;
    const float  uu = g_u[b * NB + n0 + (tid >> 1)];   // transform row u

    float acc[2][8][4];
#pragma unroll
    for (int mt = 0; mt < 2; ++mt)
#pragma unroll
        for (int nt = 0; nt < 8; ++nt)
#pragma unroll
            for (int q = 0; q < 4; ++q) acc[mt][nt][q] = 0.f;

    auto stage = [&](int slot, int kc) {
        const uint32_t st = sbase + (uint32_t)slot * 36864u;
        const __nv_bfloat16* srcs[2] = {Ah, Al};
#pragma unroll
        for (int a = 0; a < 2; ++a) {
            const __nv_bfloat16* g = srcs[a] + kc;
            const uint32_t ab = st + (uint32_t)a * 10240u;
#pragma unroll
            for (int pass = 0; pass < 2; ++pass) {
                int q = pass * 256 + tid;
                int row = q >> 2, seg = q & 3;
                CP_ASYNC16(ab + (uint32_t)(row * 80 + seg * 16),
                           g + (size_t)row * NB + seg * 8);
            }
        }
        const float* gs = Sg + kc;
        const uint32_t ss = st + 20480u;
#pragma unroll
        for (int pass = 0; pass < 4; ++pass) {
            int q = pass * 256 + tid;
            int row = q >> 3, seg = q & 7;
            CP_ASYNC16(ss + (uint32_t)(row * 128) + (uint32_t)((seg ^ (row & 7)) * 16),
                       gs + (size_t)row * NB + seg * 4);
        }
        CP_COMMIT();
    };

    // in-place: 16 f32 -> 8 packed hi + 8 packed lo within own 64B region
    auto transform = [&](int slot, int kc) {
        const int row = tid >> 1, half = tid & 1;
        const uint32_t srow = sbase + (uint32_t)slot * 36864u + 20480u
                            + (uint32_t)(row * 128);
        const uint32_t x7 = (uint32_t)(row & 7) << 4;
        const float* vp = vb + kc + half * 16;
        uint32_t hp[8], lp[8];
#pragma unroll
        for (int q = 0; q < 4; ++q) {
            float4 s4;
            asm volatile("ld.shared.v4.f32 {%0,%1,%2,%3}, [%4];"
                         : "=f"(s4.x), "=f"(s4.y), "=f"(s4.z), "=f"(s4.w)
                         : "r"(srow + ((uint32_t)((4 * half + q) << 4) ^ x7)));
            float4 v4 = *(const float4*)(vp + q * 4);
            float e0 = __expf(s4.x + uu + v4.x);
            float e1 = __expf(s4.y + uu + v4.y);
            float e2 = __expf(s4.z + uu + v4.z);
            float e3 = __expf(s4.w + uu + v4.w);
            __nv_bfloat16 h0 = __float2bfloat16(e0), h1 = __float2bfloat16(e1);
            __nv_bfloat16 h2 = __float2bfloat16(e2), h3 = __float2bfloat16(e3);
            __nv_bfloat16 l0 = __float2bfloat16(e0 - __bfloat162float(h0));
            __nv_bfloat16 l1 = __float2bfloat16(e1 - __bfloat162float(h1));
            __nv_bfloat16 l2 = __float2bfloat16(e2 - __bfloat162float(h2));
            __nv_bfloat16 l3 = __float2bfloat16(e3 - __bfloat162float(h3));
            hp[2*q]   = ((unsigned)__bfloat16_as_ushort(h1) << 16) | __bfloat16_as_ushort(h0);
            hp[2*q+1] = ((unsigned)__bfloat16_as_ushort(h3) << 16) | __bfloat16_as_ushort(h2);
            lp[2*q]   = ((unsigned)__bfloat16_as_ushort(l1) << 16) | __bfloat16_as_ushort(l0);
            lp[2*q+1] = ((unsigned)__bfloat16_as_ushort(l3) << 16) | __bfloat16_as_ushort(l2);
        }
        const uint32_t s0 = (uint32_t)(4 * half) << 4;
        asm volatile("st.shared.v4.b32 [%0], {%1,%2,%3,%4};"
                     :: "r"(srow + ((s0 + 0u)  ^ x7)), "r"(hp[0]), "r"(hp[1]), "r"(hp[2]), "r"(hp[3]));
        asm volatile("st.shared.v4.b32 [%0], {%1,%2,%3,%4};"
                     :: "r"(srow + ((s0 + 16u) ^ x7)), "r"(hp[4]), "r"(hp[5]), "r"(hp[6]), "r"(hp[7]));
        asm volatile("st.shared.v4.b32 [%0], {%1,%2,%3,%4};"
                     :: "r"(srow + ((s0 + 32u) ^ x7)), "r"(lp[0]), "r"(lp[1]), "r"(lp[2]), "r"(lp[3]));
        asm volatile("st.shared.v4.b32 [%0], {%1,%2,%3,%4};"
                     :: "r"(srow + ((s0 + 48u) ^ x7)), "r"(lp[4]), "r"(lp[5]), "r"(lp[6]), "r"(lp[7]));
    };

    // prologue: stage 0,1; transform 0
    stage(0, 0);
    stage(1, 32);
    CP_WAIT1();
    __syncthreads();
    transform(0, 0);
    __syncthreads();

    const int NCH = NB / 32;    // 32
    for (int kci = 0; kci < NCH; ++kci) {
        const int slot = kci % 3;
        if (kci + 2 < NCH) stage((kci + 2) % 3, (kci + 2) * 32);

        // ---- MMAs on chunk kci (A + transformed S in slot) ----
        const uint32_t st = sbase + (uint32_t)slot * 36864u;
        const uint32_t sa_h = st, sa_l = st + 10240u;
        const uint32_t sS  = st + 20480u;
#pragma unroll
        for (int ks = 0; ks < 2; ++ks) {
            const int k0 = ks * 16;
            uint32_t fAh[2][4], fAl[2][4];
#pragma unroll
            for (int mt = 0; mt < 2; ++mt) {
                int row = wm * 32 + mt * 16 + (lane & 15);
                uint32_t off = (uint32_t)(row * 40 + k0 + (lane >> 4) * 8) * 2u;
                LDMATRIX_X4(fAh[mt][0], fAh[mt][1], fAh[mt][2], fAh[mt][3], sa_h + off);
                LDMATRIX_X4(fAl[mt][0], fAl[mt][1], fAl[mt][2], fAl[mt][3], sa_l + off);
            }
#pragma unroll
            for (int pp = 0; pp < 4; ++pp) {
                int nrow = wn * 64 + pp * 16 + (lane & 15);
                uint32_t rbase = sS + (uint32_t)(nrow * 128);
                uint32_t rx = (uint32_t)(nrow & 7) << 4;
                uint32_t segh = (uint32_t)(4 * ks + (lane >> 4)) << 4;
                uint32_t h0, h1, h2, h3, l0, l1, l2, l3;
                LDMATRIX_X4(h0, h1, h2, h3, rbase + ((segh)        ^ rx));
                LDMATRIX_X4(l0, l1, l2, l3, rbase + ((segh + 32u)  ^ rx));
                uint32_t bh0[2] = {h0, h2}, bh1[2] = {h1, h3};
                uint32_t bl0[2] = {l0, l2}, bl1[2] = {l1, l3};
#pragma unroll
                for (int mt = 0; mt < 2; ++mt) {
                    MMA_BF16(acc[mt][2 * pp],     fAh[mt], bh0);
                    MMA_BF16(acc[mt][2 * pp],     fAh[mt], bl0);
                    MMA_BF16(acc[mt][2 * pp],     fAl[mt], bh0);
                    MMA_BF16(acc[mt][2 * pp + 1], fAh[mt], bh1);
                    MMA_BF16(acc[mt][2 * pp + 1], fAh[mt], bl1);
                    MMA_BF16(acc[mt][2 * pp + 1], fAl[mt], bh1);
                }
            }
        }

        if (kci + 1 < NCH) {
            if (kci + 2 < NCH) { CP_WAIT1(); } else { CP_WAIT0(); }
            __syncthreads();                       // S[k+1] visible, MMAs(k) read done
            transform((kci + 1) % 3, (kci + 1) * 32);
            __syncthreads();                       // B[k+1] ready
        }
    }

    float* Db = Dout + (size_t)b * DD * NB;
#pragma unroll
    for (int mt = 0; mt < 2; ++mt) {
        int r0 = m0 + wm * 32 + mt * 16 + (lane >> 2);
#pragma unroll
        for (int nt = 0; nt < 8; ++nt) {
            int c = n0 + wn * 64 + nt * 8 + (lane & 3) * 2;
            float2 w0 = make_float2(acc[mt][nt][0], acc[mt][nt][1]);
            float2 w1 = make_float2(acc[mt][nt][2], acc[mt][nt][3]);
            *(float2*)&Db[(size_t)r0 * NB + c]       = w0;
            *(float2*)&Db[(size_t)(r0 + 8) * NB + c] = w1;
        }
    }
}

// ---------------------------------------------------------------------------
// u[b][i] = -log n - LSE_j S[b][i][:]   (warp per row)
// ---------------------------------------------------------------------------
__global__ void u_lse_kernel()
{
    const int gw   = blockIdx.x * 8 + (threadIdx.x >> 5);
    const int lane = threadIdx.x & 31;
    const float4* row = (const float4*)&g_S[(size_t)gw * NB];

    float4 V[8];
#pragma unroll
    for (int s = 0; s < 8; ++s) V[s] = row[lane + 32 * s];

    float m = -1e30f;
#pragma unroll
    for (int s = 0; s < 8; ++s)
        m = fmaxf(m, fmaxf(fmaxf(V[s].x, V[s].y), fmaxf(V[s].z, V[s].w)));
#pragma unroll
    for (int o = 16; o > 0; o >>= 1) m = fmaxf(m, __shfl_xor_sync(~0u, m, o));

    float sum = 0.f;
#pragma unroll
    for (int s = 0; s < 8; ++s)
        sum += __expf(V[s].x - m) + __expf(V[s].y - m) + __expf(V[s].z - m) + __expf(V[s].w - m);
#pragma unroll
    for (int o = 16; o > 0; o >>= 1) sum += __shfl_xor_sync(~0u, sum, o);

    if (lane == 0) g_u[gw] = -6.9314718055994531f - (m + logf(sum));
}

// ---------------------------------------------------------------------------
// v[b][j] = -log n - LSE_i (S[b][i][j] + u[b][i])  via symmetry (row j)
// ---------------------------------------------------------------------------
__global__ void v_lse_kernel()
{
    const int gw   = blockIdx.x * 8 + (threadIdx.x >> 5);
    const int lane = threadIdx.x & 31;
    const int b    = gw >> 10;
    const float4* row = (const float4*)&g_S[(size_t)gw * NB];
    const float4* urw = (const float4*)&g_u[b * NB];

    float4 V[8];
#pragma unroll
    for (int s = 0; s < 8; ++s) {
        float4 sv = row[lane + 32 * s];
        float4 uv = urw[lane + 32 * s];
        V[s].x = sv.x + uv.x; V[s].y = sv.y + uv.y;
        V[s].z = sv.z + uv.z; V[s].w = sv.w + uv.w;
    }
    float m = -1e30f;
#pragma unroll
    for (int s = 0; s < 8; ++s)
        m = fmaxf(m, fmaxf(fmaxf(V[s].x, V[s].y), fmaxf(V[s].z, V[s].w)));
#pragma unroll
    for (int o = 16; o > 0; o >>= 1) m = fmaxf(m, __shfl_xor_sync(~0u, m, o));

    float sum = 0.f;
#pragma unroll
    for (int s = 0; s < 8; ++s)
        sum += __expf(V[s].x - m) + __expf(V[s].y - m) + __expf(V[s].z - m) + __expf(V[s].w - m);
#pragma unroll
    for (int o = 16; o > 0; o >>= 1) sum += __shfl_xor_sync(~0u, sum, o);

    if (lane == 0) g_v[gw] = -6.9314718055994531f - (m + logf(sum));
}

// ---------------------------------------------------------------------------
extern "C" void kernel_launch(void* const* d_in, const int* in_sizes, int n_in,
                              void* d_out, int out_size)
{
    const float* x    = (const float*)d_in[0];
    const float* rowe = (const float*)d_in[1];
    const float* cole = (const float*)d_in[2];
    float* out = (float*)d_out;

    cudaFuncSetAttribute(s_gemm_kernel,   cudaFuncAttributeMaxDynamicSharedMemorySize, 81920);
    cudaFuncSetAttribute(out_gemm_kernel, cudaFuncAttributeMaxDynamicSharedMemorySize, 110592);

    // 1) pos add + bf16 split, both layouts
    split_kernel<<<dim3(NB / 64, DD / 32, BB), 256>>>(x, rowe, cole);

    // 2) S = XI XI^T / sqrt(d), symmetric (36 block pairs), pipelined
    s_gemm_kernel<<<dim3(36, BB), 256, 81920>>>();

    // 3) u = -log n - rowLSE(S)
    u_lse_kernel<<<BB * NB / 8, 256>>>();

    // 4) v = -log n - colLSE(S + u)  (symmetry)
    v_lse_kernel<<<BB * NB / 8, 256>>>();

    // 5) out = XC @ exp(S+u+v)^T, 3-stage pipeline, in-place exp transform
    out_gemm_kernel<<<dim3(8, 4, BB), 256, 110592>>>(out);
}